// round 1
// baseline (speedup 1.0000x reference)
#include <cuda_runtime.h>
#include <cstdint>

// ---------------- problem constants ----------------
#define DIMC   512
#define NHEADS 16
#define HD     32
#define SSZ    4
#define NTOK   64            // tokens per window (8x8)
#define BWIN   2048          // 32 batches * 64 windows
#define MROWS  131072        // BWIN * NTOK == B*L
#define CHID   2048          // mlp hidden

// ---------------- scratch (device globals; no allocs allowed) ----------------
__device__ float g_XN1[(size_t)MROWS * DIMC];        // ln1+shift+partition output (tf32)
__device__ float g_QKV[(size_t)MROWS * 3 * DIMC];    // qkv activations (fp32)
__device__ float g_O  [(size_t)MROWS * DIMC];        // attention output (tf32)
__device__ float g_XN2[(size_t)MROWS * DIMC];        // ln2 output (tf32)
__device__ float g_H1 [(size_t)MROWS * CHID];        // gelu(fc1) output (tf32)
__device__ float g_Wq [3 * DIMC * DIMC];
__device__ float g_Wp [DIMC * DIMC];
__device__ float g_W1 [CHID * DIMC];
__device__ float g_W2 [DIMC * CHID];

// ---------------- helpers ----------------
__device__ __forceinline__ float tf32r(float x) {
    uint32_t u;
    asm("cvt.rna.tf32.f32 %0, %1;" : "=r"(u) : "f"(x));
    return __uint_as_float(u);
}

__device__ __forceinline__ float gelu_f(float x) {
    return 0.5f * x * (1.0f + erff(x * 0.7071067811865475f));
}

__device__ __forceinline__ void mma_tf32(float* d, const float* a, const float* b) {
    const uint32_t* A = reinterpret_cast<const uint32_t*>(a);
    const uint32_t* B = reinterpret_cast<const uint32_t*>(b);
    asm volatile(
        "mma.sync.aligned.m16n8k8.row.col.f32.tf32.tf32.f32 "
        "{%0,%1,%2,%3}, {%4,%5,%6,%7}, {%8,%9}, {%0,%1,%2,%3};\n"
        : "+f"(d[0]), "+f"(d[1]), "+f"(d[2]), "+f"(d[3])
        : "r"(A[0]), "r"(A[1]), "r"(A[2]), "r"(A[3]), "r"(B[0]), "r"(B[1]));
}

__device__ __forceinline__ uint32_t smem_u32(const void* p) {
    return (uint32_t)__cvta_generic_to_shared(p);
}

// token index in window order -> token index in (B,H,W) order (shift mapping)
__device__ __forceinline__ size_t win_to_img(int t) {
    int b_   = t >> 6, nn = t & 63;
    int bimg = b_ >> 6, widx = b_ & 63;
    int gh = ((widx >> 3) << 3) + (nn >> 3);
    int gw = ((widx & 7) << 3) + (nn & 7);
    int sh = (gh + SSZ) & 63;
    int sw = (gw + SSZ) & 63;
    return ((size_t)bimg << 12) + (size_t)(sh << 6) + (size_t)sw;
}

// ---------------- weight convert (fp32 -> tf32-rounded fp32) ----------------
template <int WHICH>
__global__ void cvt_k(const float* __restrict__ in, int n) {
    float* o = WHICH == 0 ? g_Wq : WHICH == 1 ? g_Wp : WHICH == 2 ? g_W1 : g_W2;
    int i = blockIdx.x * 256 + threadIdx.x;
    if (i < n) o[i] = tf32r(in[i]);
}

// ---------------- layernorm (warp per token), optional shift+window remap ----
template <bool SHIFT>
__global__ void __launch_bounds__(256) ln_kernel(const float* __restrict__ xin,
                                                 const float* __restrict__ gamma,
                                                 const float* __restrict__ beta) {
    int t    = (blockIdx.x * 256 + threadIdx.x) >> 5;
    int lane = threadIdx.x & 31;
    float* ob = SHIFT ? g_XN1 : g_XN2;

    size_t src = SHIFT ? win_to_img(t) : (size_t)t;
    const float* row = xin + src * DIMC;

    float4 v[4];
    float sum = 0.f, sq = 0.f;
#pragma unroll
    for (int p = 0; p < 4; p++) {
        v[p] = *(const float4*)(row + p * 128 + lane * 4);
        sum += v[p].x + v[p].y + v[p].z + v[p].w;
        sq  += v[p].x * v[p].x + v[p].y * v[p].y + v[p].z * v[p].z + v[p].w * v[p].w;
    }
#pragma unroll
    for (int o = 16; o > 0; o >>= 1) {
        sum += __shfl_xor_sync(0xffffffffu, sum, o);
        sq  += __shfl_xor_sync(0xffffffffu, sq, o);
    }
    float mu   = sum * (1.f / 512.f);
    float var  = sq * (1.f / 512.f) - mu * mu;
    float rstd = rsqrtf(var + 1e-5f);

    float* orow = ob + (size_t)t * DIMC;
#pragma unroll
    for (int p = 0; p < 4; p++) {
        int c = p * 128 + lane * 4;
        float4 g4 = *(const float4*)(gamma + c);
        float4 b4 = *(const float4*)(beta + c);
        float4 r;
        r.x = tf32r((v[p].x - mu) * rstd * g4.x + b4.x);
        r.y = tf32r((v[p].y - mu) * rstd * g4.y + b4.y);
        r.z = tf32r((v[p].z - mu) * rstd * g4.z + b4.z);
        r.w = tf32r((v[p].w - mu) * rstd * g4.w + b4.w);
        *(float4*)(orow + c) = r;
    }
}

// ---------------- GEMM: C[M,N] = A[M,K] @ W[N,K]^T (+ epilogue) -------------
// OP 0: A=g_XN1 W=g_Wq  -> g_QKV = acc + bias                     (N=1536,K=512)
// OP 1: A=g_O   W=g_Wp  -> out[remap] = aux[remap] + acc + bias   (N=512, K=512)
// OP 2: A=g_XN2 W=g_W1  -> g_H1 = tf32(gelu(acc + bias))          (N=2048,K=512)
// OP 3: A=g_H1  W=g_W2  -> out += acc + bias                      (N=512, K=2048)
template <int NTOT, int KTOT, int OP>
__global__ void __launch_bounds__(256) gemm_k(const float* __restrict__ bias,
                                              const float* __restrict__ aux,
                                              float* __restrict__ outp) {
    constexpr int BM = 128, BN = 128, BK = 32, LDSM = BK + 4;   // pad 4 floats
    extern __shared__ float sm[];
    float* As = sm;                     // [2][BM][LDSM]
    float* Bs = sm + 2 * BM * LDSM;     // [2][BN][LDSM]

    const float* A;
    const float* Bw;
    if (OP == 0)      { A = g_XN1; Bw = g_Wq; }
    else if (OP == 1) { A = g_O;   Bw = g_Wp; }
    else if (OP == 2) { A = g_XN2; Bw = g_W1; }
    else              { A = g_H1;  Bw = g_W2; }

    const int tid = threadIdx.x;
    const int m0  = blockIdx.y * BM;
    const int n0  = blockIdx.x * BN;

    const int lrow = tid >> 3;
    const int lck  = (tid & 7) * 4;

    const uint32_t sA = smem_u32(As);
    const uint32_t sB = smem_u32(Bs);

    auto load_tile = [&](int kt, int buf) {
        const float* gA = A  + (size_t)m0 * KTOT + kt * BK;
        const float* gB = Bw + (size_t)n0 * KTOT + kt * BK;
#pragma unroll
        for (int i = 0; i < 4; i++) {
            int r = i * 32 + lrow;
            uint32_t da = sA + (uint32_t)(((buf * BM + r) * LDSM + lck) * 4);
            const float* pa = gA + (size_t)r * KTOT + lck;
            asm volatile("cp.async.cg.shared.global [%0], [%1], 16;\n" ::"r"(da), "l"(pa));
            uint32_t db = sB + (uint32_t)(((buf * BN + r) * LDSM + lck) * 4);
            const float* pb = gB + (size_t)r * KTOT + lck;
            asm volatile("cp.async.cg.shared.global [%0], [%1], 16;\n" ::"r"(db), "l"(pb));
        }
        asm volatile("cp.async.commit_group;\n");
    };

    const int w    = tid >> 5;
    const int wm   = w >> 2;   // 0..1, 64 rows each
    const int wn   = w & 3;    // 0..3, 32 cols each
    const int lane = tid & 31;
    const int grp  = lane >> 2;
    const int tig  = lane & 3;

    float acc[4][4][4];
#pragma unroll
    for (int i = 0; i < 4; i++)
#pragma unroll
        for (int j = 0; j < 4; j++)
#pragma unroll
            for (int r = 0; r < 4; r++) acc[i][j][r] = 0.f;

    constexpr int KT = KTOT / BK;
    load_tile(0, 0);

#pragma unroll 1
    for (int kt = 0; kt < KT; ++kt) {
        int buf = kt & 1;
        if (kt + 1 < KT) {
            load_tile(kt + 1, buf ^ 1);
            asm volatile("cp.async.wait_group 1;\n");
        } else {
            asm volatile("cp.async.wait_group 0;\n");
        }
        __syncthreads();

        const float* Ab = As + (size_t)buf * BM * LDSM;
        const float* Bb = Bs + (size_t)buf * BN * LDSM;
#pragma unroll
        for (int ks = 0; ks < 4; ++ks) {
            float a[4][4], b[4][2];
#pragma unroll
            for (int mt = 0; mt < 4; ++mt) {
                int r = wm * 64 + mt * 16 + grp;
                int c = ks * 8 + tig;
                a[mt][0] = Ab[r * LDSM + c];
                a[mt][1] = Ab[(r + 8) * LDSM + c];
                a[mt][2] = Ab[r * LDSM + c + 4];
                a[mt][3] = Ab[(r + 8) * LDSM + c + 4];
            }
#pragma unroll
            for (int nt = 0; nt < 4; ++nt) {
                int nr = wn * 32 + nt * 8 + grp;
                int c  = ks * 8 + tig;
                b[nt][0] = Bb[nr * LDSM + c];
                b[nt][1] = Bb[nr * LDSM + c + 4];
            }
#pragma unroll
            for (int mt = 0; mt < 4; ++mt)
#pragma unroll
                for (int nt = 0; nt < 4; ++nt) mma_tf32(acc[mt][nt], a[mt], b[nt]);
        }
        __syncthreads();
    }

    // ---- epilogue ----
#pragma unroll
    for (int mt = 0; mt < 4; ++mt) {
        int r_lo = m0 + wm * 64 + mt * 16 + grp;
        int r_hi = r_lo + 8;
#pragma unroll
        for (int nt = 0; nt < 4; ++nt) {
            int c0 = n0 + wn * 32 + nt * 8 + 2 * tig;
            float b0 = bias[c0], b1 = bias[c0 + 1];
            float v00 = acc[mt][nt][0] + b0;
            float v01 = acc[mt][nt][1] + b1;
            float v10 = acc[mt][nt][2] + b0;
            float v11 = acc[mt][nt][3] + b1;
            if (OP == 0) {
                g_QKV[(size_t)r_lo * NTOT + c0]     = v00;
                g_QKV[(size_t)r_lo * NTOT + c0 + 1] = v01;
                g_QKV[(size_t)r_hi * NTOT + c0]     = v10;
                g_QKV[(size_t)r_hi * NTOT + c0 + 1] = v11;
            } else if (OP == 1) {
                size_t d0 = win_to_img(r_lo) * DIMC + c0;
                size_t d1 = win_to_img(r_hi) * DIMC + c0;
                outp[d0]     = aux[d0] + v00;
                outp[d0 + 1] = aux[d0 + 1] + v01;
                outp[d1]     = aux[d1] + v10;
                outp[d1 + 1] = aux[d1 + 1] + v11;
            } else if (OP == 2) {
                g_H1[(size_t)r_lo * NTOT + c0]     = tf32r(gelu_f(v00));
                g_H1[(size_t)r_lo * NTOT + c0 + 1] = tf32r(gelu_f(v01));
                g_H1[(size_t)r_hi * NTOT + c0]     = tf32r(gelu_f(v10));
                g_H1[(size_t)r_hi * NTOT + c0 + 1] = tf32r(gelu_f(v11));
            } else {
                size_t o0 = (size_t)r_lo * NTOT + c0;
                size_t o1 = (size_t)r_hi * NTOT + c0;
                outp[o0]     += v00;
                outp[o0 + 1] += v01;
                outp[o1]     += v10;
                outp[o1 + 1] += v11;
            }
        }
    }
}

// ---------------- attention: one block per (window, head) -------------------
__global__ void __launch_bounds__(64) attn_kernel(const float* __restrict__ rpb) {
    __shared__ float sk[64][36];
    __shared__ float sv[64][36];
    __shared__ float srpb[225];
    __shared__ int   slab[64];

    int bh = blockIdx.x;
    int b_ = bh >> 4;
    int h  = bh & 15;
    int n  = threadIdx.x;   // 0..63 (query row)

    const float* qkvrow = g_QKV + (size_t)(b_ * 64 + n) * (3 * DIMC) + h * HD;

    float q[32];
#pragma unroll
    for (int j = 0; j < 8; j++) {
        float4 t4 = *(const float4*)(qkvrow + j * 4);
        q[j * 4] = t4.x; q[j * 4 + 1] = t4.y; q[j * 4 + 2] = t4.z; q[j * 4 + 3] = t4.w;
    }
#pragma unroll
    for (int j = 0; j < 8; j++)
        *(float4*)&sk[n][j * 4] = *(const float4*)(qkvrow + DIMC + j * 4);
#pragma unroll
    for (int j = 0; j < 8; j++)
        *(float4*)&sv[n][j * 4] = *(const float4*)(qkvrow + 2 * DIMC + j * 4);

    for (int i = n; i < 225; i += 64) srpb[i] = rpb[i * NHEADS + h];

    {
        int widx = b_ & 63;
        int gh = ((widx >> 3) << 3) + (n >> 3);
        int gw = ((widx & 7) << 3) + (n & 7);
        int zh = gh < 56 ? 0 : (gh < 60 ? 1 : 2);
        int zw = gw < 56 ? 0 : (gw < 60 ? 1 : 2);
        slab[n] = zh * 3 + zw;
    }
    __syncthreads();

    const float scale = 0.17677669529663687f;  // 1/sqrt(32)
    int   mylab = slab[n];
    int   rh = n >> 3, rw = n & 7;

    float s[64];
#pragma unroll
    for (int m = 0; m < 64; m++) {
        float a0 = 0.f, a1 = 0.f, a2 = 0.f, a3 = 0.f;
#pragma unroll
        for (int j = 0; j < 8; j++) {
            float4 kk = *(const float4*)&sk[m][j * 4];
            a0 += q[j * 4]     * kk.x;
            a1 += q[j * 4 + 1] * kk.y;
            a2 += q[j * 4 + 2] * kk.z;
            a3 += q[j * 4 + 3] * kk.w;
        }
        int idx = (rh - (m >> 3) + 7) * 15 + (rw - (m & 7) + 7);
        float msk = (mylab == slab[m]) ? 0.f : -100.f;
        s[m] = ((a0 + a1) + (a2 + a3)) * scale + srpb[idx] + msk;
    }

    float mx = -1e30f;
#pragma unroll
    for (int m = 0; m < 64; m++) mx = fmaxf(mx, s[m]);
    float sum = 0.f;
#pragma unroll
    for (int m = 0; m < 64; m++) {
        s[m] = __expf(s[m] - mx);
        sum += s[m];
    }
    float inv = 1.f / sum;

    float o[32];
#pragma unroll
    for (int d = 0; d < 32; d++) o[d] = 0.f;
#pragma unroll
    for (int m = 0; m < 64; m++) {
        float p = s[m] * inv;
#pragma unroll
        for (int j = 0; j < 8; j++) {
            float4 vv = *(const float4*)&sv[m][j * 4];
            o[j * 4]     += p * vv.x;
            o[j * 4 + 1] += p * vv.y;
            o[j * 4 + 2] += p * vv.z;
            o[j * 4 + 3] += p * vv.w;
        }
    }

    float* orow = g_O + (size_t)(b_ * 64 + n) * DIMC + h * HD;
#pragma unroll
    for (int j = 0; j < 8; j++) {
        float4 r;
        r.x = tf32r(o[j * 4]);
        r.y = tf32r(o[j * 4 + 1]);
        r.z = tf32r(o[j * 4 + 2]);
        r.w = tf32r(o[j * 4 + 3]);
        *(float4*)(orow + j * 4) = r;
    }
}

// ---------------- host launcher ----------------
extern "C" void kernel_launch(void* const* d_in, const int* in_sizes, int n_in,
                              void* d_out, int out_size) {
    const float* x      = (const float*)d_in[0];
    const float* n1g    = (const float*)d_in[1];
    const float* n1b    = (const float*)d_in[2];
    const float* qkv_w  = (const float*)d_in[3];
    const float* qkv_b  = (const float*)d_in[4];
    const float* proj_w = (const float*)d_in[5];
    const float* proj_b = (const float*)d_in[6];
    const float* rpb    = (const float*)d_in[7];
    const float* n2g    = (const float*)d_in[8];
    const float* n2b    = (const float*)d_in[9];
    const float* fc1_w  = (const float*)d_in[10];
    const float* fc1_b  = (const float*)d_in[11];
    const float* fc2_w  = (const float*)d_in[12];
    const float* fc2_b  = (const float*)d_in[13];
    float* out = (float*)d_out;

    constexpr int SMEMB = 2 * (128 * 36 + 128 * 36) * 4;  // 73728 bytes

    cudaFuncSetAttribute(gemm_k<1536, 512, 0>, cudaFuncAttributeMaxDynamicSharedMemorySize, SMEMB);
    cudaFuncSetAttribute(gemm_k<512,  512, 1>, cudaFuncAttributeMaxDynamicSharedMemorySize, SMEMB);
    cudaFuncSetAttribute(gemm_k<2048, 512, 2>, cudaFuncAttributeMaxDynamicSharedMemorySize, SMEMB);
    cudaFuncSetAttribute(gemm_k<512, 2048, 3>, cudaFuncAttributeMaxDynamicSharedMemorySize, SMEMB);

    // weights -> tf32-rounded copies
    cvt_k<0><<<(3 * DIMC * DIMC + 255) / 256, 256>>>(qkv_w, 3 * DIMC * DIMC);
    cvt_k<1><<<(DIMC * DIMC + 255) / 256, 256>>>(proj_w, DIMC * DIMC);
    cvt_k<2><<<(CHID * DIMC + 255) / 256, 256>>>(fc1_w, CHID * DIMC);
    cvt_k<3><<<(DIMC * CHID + 255) / 256, 256>>>(fc2_w, DIMC * CHID);

    // LN1 + shift + window partition
    ln_kernel<true><<<MROWS / 8, 256>>>(x, n1g, n1b);

    // QKV projection
    gemm_k<1536, 512, 0><<<dim3(1536 / 128, MROWS / 128), 256, SMEMB>>>(qkv_b, nullptr, nullptr);

    // windowed attention
    attn_kernel<<<BWIN * NHEADS, 64>>>(rpb);

    // output projection + window reverse + shift + residual -> d_out = x1
    gemm_k<512, 512, 1><<<dim3(512 / 128, MROWS / 128), 256, SMEMB>>>(proj_b, x, out);

    // LN2
    ln_kernel<false><<<MROWS / 8, 256>>>(out, n2g, n2b);

    // FC1 + gelu
    gemm_k<2048, 512, 2><<<dim3(2048 / 128, MROWS / 128), 256, SMEMB>>>(fc1_b, nullptr, nullptr);

    // FC2 + residual add into d_out
    gemm_k<512, 2048, 3><<<dim3(512 / 128, MROWS / 128), 256, SMEMB>>>(fc2_b, nullptr, out);
}

// round 3
// speedup vs baseline: 1.8800x; 1.8800x over previous
#include <cuda_runtime.h>
#include <cuda_fp16.h>
#include <cstdint>

// ---------------- problem constants ----------------
#define DIMC   512
#define NHEADS 16
#define SSZ    4
#define BWIN   2048          // 32 batches * 64 windows
#define MROWS  131072        // BWIN * 64 == B*L
#define CHID   2048          // mlp hidden

// ---------------- scratch (device globals; no allocs allowed) ----------------
__device__ __half g_XN1[(size_t)MROWS * DIMC];
__device__ __half g_QKV[(size_t)MROWS * 3 * DIMC];
__device__ __half g_O  [(size_t)MROWS * DIMC];
__device__ __half g_XN2[(size_t)MROWS * DIMC];
__device__ __half g_H1 [(size_t)MROWS * CHID];
__device__ __half g_Wq [3 * DIMC * DIMC];
__device__ __half g_Wp [DIMC * DIMC];
__device__ __half g_W1 [CHID * DIMC];
__device__ __half g_W2 [DIMC * CHID];

// ---------------- helpers ----------------
__device__ __forceinline__ float gelu_f(float x) {
    return 0.5f * x * (1.0f + erff(x * 0.7071067811865475f));
}

__device__ __forceinline__ uint32_t smem_u32(const void* p) {
    return (uint32_t)__cvta_generic_to_shared(p);
}

// token index in window order -> token index in (B,H,W) order (shift mapping)
__device__ __forceinline__ size_t win_to_img(int t) {
    int b_   = t >> 6, nn = t & 63;
    int bimg = b_ >> 6, widx = b_ & 63;
    int gh = ((widx >> 3) << 3) + (nn >> 3);
    int gw = ((widx & 7) << 3) + (nn & 7);
    int sh = (gh + SSZ) & 63;
    int sw = (gw + SSZ) & 63;
    return ((size_t)bimg << 12) + (size_t)(sh << 6) + (size_t)sw;
}

#define LDSM_X4(r0, r1, r2, r3, addr)                                          \
    asm volatile("ldmatrix.sync.aligned.m8n8.x4.shared.b16 {%0,%1,%2,%3}, [%4];" \
                 : "=r"(r0), "=r"(r1), "=r"(r2), "=r"(r3) : "r"(addr))

#define LDSM_X2(r0, r1, addr)                                                  \
    asm volatile("ldmatrix.sync.aligned.m8n8.x2.shared.b16 {%0,%1}, [%2];"     \
                 : "=r"(r0), "=r"(r1) : "r"(addr))

#define MMA16816(d, a, b)                                                      \
    asm volatile(                                                              \
        "mma.sync.aligned.m16n8k16.row.col.f32.f16.f16.f32 "                   \
        "{%0,%1,%2,%3},{%4,%5,%6,%7},{%8,%9},{%0,%1,%2,%3};"                   \
        : "+f"((d)[0]), "+f"((d)[1]), "+f"((d)[2]), "+f"((d)[3])               \
        : "r"((a)[0]), "r"((a)[1]), "r"((a)[2]), "r"((a)[3]),                  \
          "r"((b)[0]), "r"((b)[1]))

// ---------------- weight convert (fp32 -> fp16) ----------------
template <int WHICH>
__global__ void cvt_k(const float* __restrict__ in, int n) {
    __half* o = WHICH == 0 ? g_Wq : WHICH == 1 ? g_Wp : WHICH == 2 ? g_W1 : g_W2;
    int i = blockIdx.x * 256 + threadIdx.x;
    if (i < n) o[i] = __float2half(in[i]);
}

// ---------------- layernorm (warp per token), optional shift+window remap ----
template <bool SHIFT>
__global__ void __launch_bounds__(256) ln_kernel(const float* __restrict__ xin,
                                                 const float* __restrict__ gamma,
                                                 const float* __restrict__ beta) {
    int t    = (blockIdx.x * 256 + threadIdx.x) >> 5;
    int lane = threadIdx.x & 31;
    __half* ob = SHIFT ? g_XN1 : g_XN2;

    size_t src = SHIFT ? win_to_img(t) : (size_t)t;
    const float* row = xin + src * DIMC;

    float4 v[4];
    float sum = 0.f, sq = 0.f;
#pragma unroll
    for (int p = 0; p < 4; p++) {
        v[p] = *(const float4*)(row + p * 128 + lane * 4);
        sum += v[p].x + v[p].y + v[p].z + v[p].w;
        sq  += v[p].x * v[p].x + v[p].y * v[p].y + v[p].z * v[p].z + v[p].w * v[p].w;
    }
#pragma unroll
    for (int o = 16; o > 0; o >>= 1) {
        sum += __shfl_xor_sync(0xffffffffu, sum, o);
        sq  += __shfl_xor_sync(0xffffffffu, sq, o);
    }
    float mu   = sum * (1.f / 512.f);
    float var  = sq * (1.f / 512.f) - mu * mu;
    float rstd = rsqrtf(var + 1e-5f);

    __half* orow = ob + (size_t)t * DIMC;
#pragma unroll
    for (int p = 0; p < 4; p++) {
        int c = p * 128 + lane * 4;
        float4 g4 = *(const float4*)(gamma + c);
        float4 b4 = *(const float4*)(beta + c);
        __half2 h0 = __floats2half2_rn((v[p].x - mu) * rstd * g4.x + b4.x,
                                       (v[p].y - mu) * rstd * g4.y + b4.y);
        __half2 h1 = __floats2half2_rn((v[p].z - mu) * rstd * g4.z + b4.z,
                                       (v[p].w - mu) * rstd * g4.w + b4.w);
        uint2 u;
        u.x = *(uint32_t*)&h0;
        u.y = *(uint32_t*)&h1;
        *(uint2*)(orow + c) = u;
    }
}

// ---------------- fp16 mma.sync GEMM: C[M,N] = A[M,K] @ W[N,K]^T ------------
// BM=128, BN=128, BK=32, 3-stage cp.async pipeline, XOR-swizzled smem,
// ldmatrix fragment loads, m16n8k16 fp16 mma with fp32 accumulate.
// OP 0: A=g_XN1 W=g_Wq  -> g_QKV(f16) = acc + bias
// OP 1: A=g_O   W=g_Wp  -> out[remap] = aux[remap] + acc + bias   (fp32)
// OP 2: A=g_XN2 W=g_W1  -> g_H1(f16) = gelu(acc + bias)
// OP 3: A=g_H1  W=g_W2  -> out += acc + bias                       (fp32)
template <int NTOT, int KTOT, int OP>
__global__ void __launch_bounds__(256, 2) gemm_f16(const float* __restrict__ bias,
                                                   const float* __restrict__ aux,
                                                   float* __restrict__ outp) {
    constexpr int BM = 128, BN = 128, BK = 32, STAGES = 3;
    constexpr int KT = KTOT / BK;
    constexpr uint32_t AB    = BM * BK * 2;   // 8KB
    constexpr uint32_t BB    = BN * BK * 2;   // 8KB
    constexpr uint32_t STAGE = AB + BB;       // 16KB

    extern __shared__ char smem[];
    const uint32_t sbase = smem_u32(smem);
    const int tid = threadIdx.x;

    const __half* A;
    const __half* Bw;
    if (OP == 0)      { A = g_XN1; Bw = g_Wq; }
    else if (OP == 1) { A = g_O;   Bw = g_Wp; }
    else if (OP == 2) { A = g_XN2; Bw = g_W1; }
    else              { A = g_H1;  Bw = g_W2; }

    const int m0 = blockIdx.y * BM;
    const int n0 = blockIdx.x * BN;

    auto load_tile = [&](int kt, int s) {
        const __half* gA = A + (size_t)m0 * KTOT + kt * BK;
#pragma unroll
        for (int i = 0; i < 2; i++) {
            int idx = i * 256 + tid;
            int r = idx >> 2, g = idx & 3;
            uint32_t dst = sbase + (uint32_t)s * STAGE +
                           (uint32_t)(r * 64 + ((g ^ ((r >> 1) & 3)) << 4));
            const __half* src = gA + (size_t)r * KTOT + g * 8;
            asm volatile("cp.async.cg.shared.global [%0], [%1], 16;\n" ::"r"(dst), "l"(src));
        }
        const __half* gB = Bw + (size_t)n0 * KTOT + kt * BK;
#pragma unroll
        for (int i = 0; i < 2; i++) {
            int idx = i * 256 + tid;
            int r = idx >> 2, g = idx & 3;
            uint32_t dst = sbase + (uint32_t)s * STAGE + AB +
                           (uint32_t)(r * 64 + ((g ^ ((r >> 1) & 3)) << 4));
            const __half* src = gB + (size_t)r * KTOT + g * 8;
            asm volatile("cp.async.cg.shared.global [%0], [%1], 16;\n" ::"r"(dst), "l"(src));
        }
        asm volatile("cp.async.commit_group;\n");
    };

    const int w    = tid >> 5;
    const int wm   = w >> 2;    // 0..1 (64 rows)
    const int wn   = w & 3;     // 0..3 (32 cols)
    const int lane = tid & 31;
    const int grp  = lane >> 2;
    const int tig  = lane & 3;

    float acc[4][4][4];
#pragma unroll
    for (int i = 0; i < 4; i++)
#pragma unroll
        for (int j = 0; j < 4; j++)
#pragma unroll
            for (int r = 0; r < 4; r++) acc[i][j][r] = 0.f;

    // precompute ldmatrix lane addressing (relative within stage)
    const int a_row  = wm * 64 + (lane & 15);       // + mt*16
    const int a_chk0 = lane >> 4;                    // + ks*2
    const int l2     = lane & 15;
    const int b_row  = wn * 32 + (l2 & 7);           // + nt*8
    const int b_chk0 = l2 >> 3;                      // + ks*2

    load_tile(0, 0);
    load_tile(1, 1);

#pragma unroll 1
    for (int kt = 0; kt < KT; ++kt) {
        if (kt + 2 < KT) asm volatile("cp.async.wait_group 1;\n");
        else             asm volatile("cp.async.wait_group 0;\n");
        __syncthreads();

        if (kt + 2 < KT) load_tile(kt + 2, (kt + 2) % STAGES);

        const uint32_t stA = sbase + (uint32_t)(kt % STAGES) * STAGE;
        const uint32_t stB = stA + AB;

#pragma unroll
        for (int ks = 0; ks < 2; ++ks) {
            uint32_t a[4][4], b[4][2];
#pragma unroll
            for (int mt = 0; mt < 4; ++mt) {
                int r = a_row + mt * 16;
                int c = ks * 2 + a_chk0;
                uint32_t ad = stA + (uint32_t)(r * 64 + ((c ^ ((r >> 1) & 3)) << 4));
                LDSM_X4(a[mt][0], a[mt][1], a[mt][2], a[mt][3], ad);
            }
#pragma unroll
            for (int nt = 0; nt < 4; ++nt) {
                int r = b_row + nt * 8;
                int c = ks * 2 + b_chk0;
                uint32_t bd = stB + (uint32_t)(r * 64 + ((c ^ ((r >> 1) & 3)) << 4));
                LDSM_X2(b[nt][0], b[nt][1], bd);
            }
#pragma unroll
            for (int mt = 0; mt < 4; ++mt)
#pragma unroll
                for (int nt = 0; nt < 4; ++nt) MMA16816(acc[mt][nt], a[mt], b[nt]);
        }
    }

    // ---- epilogue ----
#pragma unroll
    for (int mt = 0; mt < 4; ++mt) {
        int r_lo = m0 + wm * 64 + mt * 16 + grp;
        int r_hi = r_lo + 8;
#pragma unroll
        for (int nt = 0; nt < 4; ++nt) {
            int c0 = n0 + wn * 32 + nt * 8 + 2 * tig;
            float b0 = bias[c0], b1 = bias[c0 + 1];
            float v00 = acc[mt][nt][0] + b0;
            float v01 = acc[mt][nt][1] + b1;
            float v10 = acc[mt][nt][2] + b0;
            float v11 = acc[mt][nt][3] + b1;
            if (OP == 0) {
                __half2 h0 = __floats2half2_rn(v00, v01);
                __half2 h1 = __floats2half2_rn(v10, v11);
                *(__half2*)(g_QKV + (size_t)r_lo * NTOT + c0) = h0;
                *(__half2*)(g_QKV + (size_t)r_hi * NTOT + c0) = h1;
            } else if (OP == 1) {
                size_t d0 = win_to_img(r_lo) * DIMC + c0;
                size_t d1 = win_to_img(r_hi) * DIMC + c0;
                float2 a0 = *(const float2*)(aux + d0);
                float2 a1 = *(const float2*)(aux + d1);
                float2 o0 = make_float2(a0.x + v00, a0.y + v01);
                float2 o1 = make_float2(a1.x + v10, a1.y + v11);
                *(float2*)(outp + d0) = o0;
                *(float2*)(outp + d1) = o1;
            } else if (OP == 2) {
                __half2 h0 = __floats2half2_rn(gelu_f(v00), gelu_f(v01));
                __half2 h1 = __floats2half2_rn(gelu_f(v10), gelu_f(v11));
                *(__half2*)(g_H1 + (size_t)r_lo * NTOT + c0) = h0;
                *(__half2*)(g_H1 + (size_t)r_hi * NTOT + c0) = h1;
            } else {
                size_t o0 = (size_t)r_lo * NTOT + c0;
                size_t o1 = (size_t)r_hi * NTOT + c0;
                float2 p0 = *(const float2*)(outp + o0);
                float2 p1 = *(const float2*)(outp + o1);
                p0.x += v00; p0.y += v01;
                p1.x += v10; p1.y += v11;
                *(float2*)(outp + o0) = p0;
                *(float2*)(outp + o1) = p1;
            }
        }
    }
}

// ---------------- attention: one block per (window, head) -------------------
__global__ void __launch_bounds__(64) attn_kernel(const float* __restrict__ rpb) {
    __shared__ float sk[64][36];
    __shared__ float sv[64][36];
    __shared__ float srpb[225];
    __shared__ int   slab[64];

    int bh = blockIdx.x;
    int b_ = bh >> 4;
    int h  = bh & 15;
    int n  = threadIdx.x;

    const __half* qkvrow = g_QKV + (size_t)(b_ * 64 + n) * (3 * DIMC) + h * 32;

    float q[32];
#pragma unroll
    for (int j = 0; j < 4; j++) {
        uint4 u = *(const uint4*)(qkvrow + j * 8);
        const __half2* hp = (const __half2*)&u;
#pragma unroll
        for (int e = 0; e < 4; e++) {
            float2 f = __half22float2(hp[e]);
            q[j * 8 + e * 2]     = f.x;
            q[j * 8 + e * 2 + 1] = f.y;
        }
    }
#pragma unroll
    for (int j = 0; j < 4; j++) {
        uint4 u = *(const uint4*)(qkvrow + DIMC + j * 8);
        const __half2* hp = (const __half2*)&u;
#pragma unroll
        for (int e = 0; e < 4; e++) {
            float2 f = __half22float2(hp[e]);
            sk[n][j * 8 + e * 2]     = f.x;
            sk[n][j * 8 + e * 2 + 1] = f.y;
        }
    }
#pragma unroll
    for (int j = 0; j < 4; j++) {
        uint4 u = *(const uint4*)(qkvrow + 2 * DIMC + j * 8);
        const __half2* hp = (const __half2*)&u;
#pragma unroll
        for (int e = 0; e < 4; e++) {
            float2 f = __half22float2(hp[e]);
            sv[n][j * 8 + e * 2]     = f.x;
            sv[n][j * 8 + e * 2 + 1] = f.y;
        }
    }

    for (int i = n; i < 225; i += 64) srpb[i] = rpb[i * NHEADS + h];

    {
        int widx = b_ & 63;
        int gh = ((widx >> 3) << 3) + (n >> 3);
        int gw = ((widx & 7) << 3) + (n & 7);
        int zh = gh < 56 ? 0 : (gh < 60 ? 1 : 2);
        int zw = gw < 56 ? 0 : (gw < 60 ? 1 : 2);
        slab[n] = zh * 3 + zw;
    }
    __syncthreads();

    const float scale = 0.17677669529663687f;  // 1/sqrt(32)
    int   mylab = slab[n];
    int   rh = n >> 3, rw = n & 7;

    float s[64];
#pragma unroll
    for (int m = 0; m < 64; m++) {
        float a0 = 0.f, a1 = 0.f, a2 = 0.f, a3 = 0.f;
#pragma unroll
        for (int j = 0; j < 8; j++) {
            float4 kk = *(const float4*)&sk[m][j * 4];
            a0 += q[j * 4]     * kk.x;
            a1 += q[j * 4 + 1] * kk.y;
            a2 += q[j * 4 + 2] * kk.z;
            a3 += q[j * 4 + 3] * kk.w;
        }
        int idx = (rh - (m >> 3) + 7) * 15 + (rw - (m & 7) + 7);
        float msk = (mylab == slab[m]) ? 0.f : -100.f;
        s[m] = ((a0 + a1) + (a2 + a3)) * scale + srpb[idx] + msk;
    }

    float mx = -1e30f;
#pragma unroll
    for (int m = 0; m < 64; m++) mx = fmaxf(mx, s[m]);
    float sum = 0.f;
#pragma unroll
    for (int m = 0; m < 64; m++) {
        s[m] = __expf(s[m] - mx);
        sum += s[m];
    }
    float inv = 1.f / sum;

    float o[32];
#pragma unroll
    for (int d = 0; d < 32; d++) o[d] = 0.f;
#pragma unroll
    for (int m = 0; m < 64; m++) {
        float p = s[m] * inv;
#pragma unroll
        for (int j = 0; j < 8; j++) {
            float4 vv = *(const float4*)&sv[m][j * 4];
            o[j * 4]     += p * vv.x;
            o[j * 4 + 1] += p * vv.y;
            o[j * 4 + 2] += p * vv.z;
            o[j * 4 + 3] += p * vv.w;
        }
    }

    __half* orow = g_O + (size_t)(b_ * 64 + n) * DIMC + h * 32;
#pragma unroll
    for (int j = 0; j < 4; j++) {
        __half2 h0 = __floats2half2_rn(o[j * 8],     o[j * 8 + 1]);
        __half2 h1 = __floats2half2_rn(o[j * 8 + 2], o[j * 8 + 3]);
        __half2 h2 = __floats2half2_rn(o[j * 8 + 4], o[j * 8 + 5]);
        __half2 h3 = __floats2half2_rn(o[j * 8 + 6], o[j * 8 + 7]);
        uint4 u;
        u.x = *(uint32_t*)&h0;
        u.y = *(uint32_t*)&h1;
        u.z = *(uint32_t*)&h2;
        u.w = *(uint32_t*)&h3;
        *(uint4*)(orow + j * 8) = u;
    }
}

// ---------------- host launcher ----------------
extern "C" void kernel_launch(void* const* d_in, const int* in_sizes, int n_in,
                              void* d_out, int out_size) {
    const float* x      = (const float*)d_in[0];
    const float* n1g    = (const float*)d_in[1];
    const float* n1b    = (const float*)d_in[2];
    const float* qkv_w  = (const float*)d_in[3];
    const float* qkv_b  = (const float*)d_in[4];
    const float* proj_w = (const float*)d_in[5];
    const float* proj_b = (const float*)d_in[6];
    const float* rpb    = (const float*)d_in[7];
    const float* n2g    = (const float*)d_in[8];
    const float* n2b    = (const float*)d_in[9];
    const float* fc1_w  = (const float*)d_in[10];
    const float* fc1_b  = (const float*)d_in[11];
    const float* fc2_w  = (const float*)d_in[12];
    const float* fc2_b  = (const float*)d_in[13];
    float* out = (float*)d_out;

    constexpr int SMEMB = 3 * (128 * 32 * 2 + 128 * 32 * 2);  // 49152 bytes

    cudaFuncSetAttribute(gemm_f16<1536, 512, 0>, cudaFuncAttributeMaxDynamicSharedMemorySize, SMEMB);
    cudaFuncSetAttribute(gemm_f16<512,  512, 1>, cudaFuncAttributeMaxDynamicSharedMemorySize, SMEMB);
    cudaFuncSetAttribute(gemm_f16<2048, 512, 2>, cudaFuncAttributeMaxDynamicSharedMemorySize, SMEMB);
    cudaFuncSetAttribute(gemm_f16<512, 2048, 3>, cudaFuncAttributeMaxDynamicSharedMemorySize, SMEMB);

    // weights -> fp16 copies
    cvt_k<0><<<(3 * DIMC * DIMC + 255) / 256, 256>>>(qkv_w, 3 * DIMC * DIMC);
    cvt_k<1><<<(DIMC * DIMC + 255) / 256, 256>>>(proj_w, DIMC * DIMC);
    cvt_k<2><<<(CHID * DIMC + 255) / 256, 256>>>(fc1_w, CHID * DIMC);
    cvt_k<3><<<(DIMC * CHID + 255) / 256, 256>>>(fc2_w, DIMC * CHID);

    // LN1 + shift + window partition
    ln_kernel<true><<<MROWS / 8, 256>>>(x, n1g, n1b);

    // QKV projection
    gemm_f16<1536, 512, 0><<<dim3(1536 / 128, MROWS / 128), 256, SMEMB>>>(qkv_b, nullptr, nullptr);

    // windowed attention
    attn_kernel<<<BWIN * NHEADS, 64>>>(rpb);

    // output projection + window reverse + shift + residual -> d_out
    gemm_f16<512, 512, 1><<<dim3(512 / 128, MROWS / 128), 256, SMEMB>>>(proj_b, x, out);

    // LN2
    ln_kernel<false><<<MROWS / 8, 256>>>(out, n2g, n2b);

    // FC1 + gelu
    gemm_f16<2048, 512, 2><<<dim3(2048 / 128, MROWS / 128), 256, SMEMB>>>(fc1_b, nullptr, nullptr);

    // FC2 + residual add into d_out
    gemm_f16<512, 2048, 3><<<dim3(512 / 128, MROWS / 128), 256, SMEMB>>>(fc2_b, nullptr, out);
}